// round 13
// baseline (speedup 1.0000x reference)
#include <cuda_runtime.h>
#include <cstdint>

// Problem dims (fixed by the dataset)
#define T_DIM 128
#define B_DIM 64
#define H_DIM 1024
#define M_DIM (T_DIM * B_DIM)   // 8192
#define BH    (B_DIM * H_DIM)   // 65536

#define DELTA  1e-3f
#define ROWCAP 128

// Scratch (allocation-free rule: __device__ globals)
__device__ float g_xfix[(size_t)B_DIM * 1024 * T_DIM]; // 32 MB exact xcol per flagged slot
__device__ float g_xproj[(size_t)M_DIM * H_DIM];       // 32 MB approx x_proj
__device__ float g_spk[(size_t)M_DIM * H_DIM];         // 32 MB approx spikes
__device__ float g_w1t[(size_t)H_DIM * H_DIM];         // 4 MB tf32-rounded W1
__device__ float g_w2t[(size_t)H_DIM * H_DIM];         // 4 MB tf32-rounded W2
__device__ int   g_cnt[B_DIM];
__device__ int   g_list[B_DIM * H_DIM];
__device__ int   g_rowcnt[T_DIM * B_DIM];              // per-(t,b) delta count
__device__ int   g_rowdelta[(size_t)T_DIM * B_DIM * ROWCAP];

// ============================================================================
// Helpers
// ============================================================================
__device__ __forceinline__ uint32_t smem_u32(const void* p) {
    uint32_t a;
    asm("{ .reg .u64 t; cvta.to.shared.u64 t, %1; cvt.u32.u64 %0, t; }"
        : "=r"(a) : "l"(p));
    return a;
}
__device__ __forceinline__ void cp_async16(uint32_t dst, const void* src) {
    asm volatile("cp.async.cg.shared.global [%0], [%1], 16;"
                 :: "r"(dst), "l"(src) : "memory");
}
#define CP_ASYNC_COMMIT() asm volatile("cp.async.commit_group;" ::: "memory")
#define CP_ASYNC_WAIT(n)  asm volatile("cp.async.wait_group %0;" :: "n"(n) : "memory")

__device__ __forceinline__ void mma_tf32(float* d, const uint32_t* a, const uint32_t* b) {
    asm volatile(
        "mma.sync.aligned.m16n8k8.row.col.f32.tf32.tf32.f32 "
        "{%0,%1,%2,%3}, {%4,%5,%6,%7}, {%8,%9}, {%0,%1,%2,%3};"
        : "+f"(d[0]), "+f"(d[1]), "+f"(d[2]), "+f"(d[3])
        : "r"(a[0]), "r"(a[1]), "r"(a[2]), "r"(a[3]),
          "r"(b[0]), "r"(b[1]));
}

// ============================================================================
// GEMM tile body (tuned R10 config): C = A * B^T, CTA 128x128, BK=32,
// 128 threads, 3-stage cp.async, XOR-swizzled smem. Shared by gemm1 and the
// fused kernel's GEMM2 path.
// ============================================================================
#define BM        128
#define BN        128
#define BKF       32
#define A_U32     (BM * BKF)
#define B_U32     (BN * BKF)
#define STAGE_U32 (A_U32 + B_U32)
#define STAGE_BYTES (STAGE_U32 * 4)
#define NSTAGE    3
#define SMEM_DYN  (NSTAGE * STAGE_BYTES)   // 96 KB
#define NT_GEMM   128

__device__ __forceinline__ void gemm_tile_body(
    float* sm, const float* __restrict__ A, const float* __restrict__ Bm,
    float* __restrict__ C, int m0, int n0)
{
    const uint32_t smu = smem_u32(sm);
    const int tid  = threadIdx.x;
    const int lane = tid & 31;
    const int wid  = tid >> 5;
    const int g = lane >> 2;
    const int t = lane & 3;
    const int wm = (wid >> 1) * 64;
    const int wn = (wid & 1) * 64;

    const float* Abase = A  + (size_t)m0 * H_DIM;
    const float* Bbase = Bm + (size_t)n0 * H_DIM;

    int lra[8], lqa[8];
    uint32_t sda[8];
#pragma unroll
    for (int p = 0; p < 8; p++) {
        int f = tid + p * NT_GEMM;
        lra[p] = f >> 3;
        lqa[p] = f & 7;
        sda[p] = (uint32_t)((lra[p] * 32 + ((lqa[p] ^ (lra[p] & 7)) << 2)) * 4);
    }

    float acc[4][8][4];
#pragma unroll
    for (int i = 0; i < 4; i++)
#pragma unroll
        for (int j = 0; j < 8; j++)
#pragma unroll
            for (int r = 0; r < 4; r++) acc[i][j][r] = 0.0f;

    auto prefetch = [&](int chunk, int stage) {
        const uint32_t base = smu + (uint32_t)stage * STAGE_BYTES;
#pragma unroll
        for (int p = 0; p < 8; p++)
            cp_async16(base + sda[p],
                       Abase + (size_t)lra[p] * H_DIM + chunk * BKF + lqa[p] * 4);
#pragma unroll
        for (int p = 0; p < 8; p++)
            cp_async16(base + (uint32_t)(A_U32 * 4) + sda[p],
                       Bbase + (size_t)lra[p] * H_DIM + chunk * BKF + lqa[p] * 4);
    };

    const int NCH = H_DIM / BKF;
    prefetch(0, 0);
    CP_ASYNC_COMMIT();
    prefetch(1, 1);
    CP_ASYNC_COMMIT();

    int stage = 0;
    for (int it = 0; it < NCH; ++it) {
        if (it + 1 < NCH) { CP_ASYNC_WAIT(1); } else { CP_ASYNC_WAIT(0); }
        __syncthreads();
        if (it + 2 < NCH) {
            int s2 = stage + 2; if (s2 >= NSTAGE) s2 -= NSTAGE;
            prefetch(it + 2, s2);
            CP_ASYNC_COMMIT();
        }

        const uint32_t* As = (const uint32_t*)sm + (size_t)stage * STAGE_U32;
        const uint32_t* Bs = As + A_U32;

#pragma unroll
        for (int ks = 0; ks < 4; ks++) {
            const int c0 = ((ks * 2) ^ g) << 2;
            const int c1 = ((ks * 2 + 1) ^ g) << 2;

            uint32_t af[4][4];
#pragma unroll
            for (int mt = 0; mt < 4; mt++) {
                const int mb = wm + mt * 16 + g;
                af[mt][0] = As[mb * 32 + c0 + t];
                af[mt][1] = As[(mb + 8) * 32 + c0 + t];
                af[mt][2] = As[mb * 32 + c1 + t];
                af[mt][3] = As[(mb + 8) * 32 + c1 + t];
            }
            uint32_t bf[8][2];
#pragma unroll
            for (int nt = 0; nt < 8; nt++) {
                const int nb = wn + nt * 8 + g;
                bf[nt][0] = Bs[nb * 32 + c0 + t];
                bf[nt][1] = Bs[nb * 32 + c1 + t];
            }
#pragma unroll
            for (int mt = 0; mt < 4; mt++)
#pragma unroll
                for (int nt = 0; nt < 8; nt++)
                    mma_tf32(acc[mt][nt], af[mt], bf[nt]);
        }

        if (++stage >= NSTAGE) stage = 0;
    }

#pragma unroll
    for (int mt = 0; mt < 4; mt++) {
#pragma unroll
        for (int nt = 0; nt < 8; nt++) {
            const int row = m0 + wm + mt * 16 + g;
            const int col = n0 + wn + nt * 8 + 2 * t;
            float2 v01 = make_float2(acc[mt][nt][0], acc[mt][nt][1]);
            float2 v23 = make_float2(acc[mt][nt][2], acc[mt][nt][3]);
            *(float2*)&C[(size_t)row * H_DIM + col] = v01;
            *(float2*)&C[(size_t)(row + 8) * H_DIM + col] = v23;
        }
    }
}

// Standalone GEMM1 (A = raw fp32 x, HW truncates; B = tf32-rounded W1)
__global__ void __launch_bounds__(NT_GEMM, 2)
gemm_tf32_mma(const float* __restrict__ A,
              const float* __restrict__ Bm,
              float* __restrict__ C)
{
    extern __shared__ float sm[];
    gemm_tile_body(sm, A, Bm, C, blockIdx.y * BM, blockIdx.x * BN);
}

// ============================================================================
// Fixup tile body: exact fp32 x_proj columns for flagged lanes -> xfix.
// 128 threads, tile 64h x 32t. Decodes (b, tq, hs) from fixup id.
// Smem (aliased into the 96 KB dynamic buffer):
//   Ws 64j x 64k (16 KB), Xs 32t x 64k (8 KB), hlist 64 ints.
// XOR-block swizzle: row r: phys = r*64 + ((kq ^ (r&15))<<2) + (k&3).
// ============================================================================
__device__ __forceinline__ void fixup_tile_body(
    float* sm, const float* __restrict__ x, const float* __restrict__ W1,
    const int* __restrict__ cnt, const int* __restrict__ list,
    float* __restrict__ xfix, int fid)
{
    float* Ws = sm;                 // 64*64
    float* Xs = sm + 4096;          // 32*64
    int*   hlist = (int*)(sm + 4096 + 2048);

    const int b  = fid & 63;
    const int tq = (fid >> 6) & 3;
    const int hs = fid >> 8;            // 0..1
    const int tid = threadIdx.x;
    const int jg = tid & 15;            // j = jg + 16*jj, jj<4
    const int tg = tid >> 4;            // 0..7, t = tq*32 + 4*tg + tt
    const int n = cnt[b];
    const int boff = b << 10;
    const int t0 = tq * 32;

    for (int base = hs * 64; base < n; base += 128) {
        if (tid < 64)
            hlist[tid] = (base + tid < n) ? list[boff + base + tid] : 0;
        __syncthreads();

        float acc[4][4];
#pragma unroll
        for (int jj = 0; jj < 4; jj++)
#pragma unroll
            for (int tt = 0; tt < 4; tt++) acc[jj][tt] = 0.0f;

        for (int kc = 0; kc < 16; kc++) {
            // Xs: 32 t x 64 k = 512 f4, 4/thread
#pragma unroll
            for (int p = 0; p < 4; p++) {
                int f = tid + p * 128;
                int tl = f >> 4, kq = f & 15;
                float4 v = *(const float4*)(x + (size_t)(t0 + tl) * BH
                                            + boff + kc * 64 + kq * 4);
                *(float4*)&Xs[tl * 64 + ((kq ^ (tl & 15)) << 2)] = v;
            }
            // Ws: 64 j x 64 k = 1024 f4, 8/thread
#pragma unroll
            for (int p = 0; p < 8; p++) {
                int f = tid + p * 128;
                int j = f >> 4, kq = f & 15;
                float4 v = *(const float4*)(W1 + (size_t)hlist[j] * H_DIM
                                            + kc * 64 + kq * 4);
                *(float4*)&Ws[j * 64 + ((kq ^ (j & 15)) << 2)] = v;
            }
            __syncthreads();

#pragma unroll
            for (int kg = 0; kg < 16; kg++) {
                float4 wv[4];
#pragma unroll
                for (int jj = 0; jj < 4; jj++) {
                    int j = jg + 16 * jj;
                    wv[jj] = *(const float4*)&Ws[j * 64 + ((kg ^ jg) << 2)];
                }
                float4 xv[4];
#pragma unroll
                for (int tt = 0; tt < 4; tt++) {
                    int r = 4 * tg + tt;
                    xv[tt] = *(const float4*)&Xs[r * 64 + ((kg ^ (r & 15)) << 2)];
                }
#pragma unroll
                for (int jj = 0; jj < 4; jj++)
#pragma unroll
                    for (int tt = 0; tt < 4; tt++) {
                        acc[jj][tt] = fmaf(wv[jj].x, xv[tt].x, acc[jj][tt]);
                        acc[jj][tt] = fmaf(wv[jj].y, xv[tt].y, acc[jj][tt]);
                        acc[jj][tt] = fmaf(wv[jj].z, xv[tt].z, acc[jj][tt]);
                        acc[jj][tt] = fmaf(wv[jj].w, xv[tt].w, acc[jj][tt]);
                    }
            }
            __syncthreads();
        }

        // write: xfix[(boff + base + j) * T_DIM + t0 + 4*tg + tt]
#pragma unroll
        for (int jj = 0; jj < 4; jj++) {
            int slot = base + jg + 16 * jj;
            float4 v = make_float4(acc[jj][0], acc[jj][1], acc[jj][2], acc[jj][3]);
            *(float4*)&xfix[((size_t)boff + slot) * T_DIM + t0 + 4 * tg] = v;
        }
        __syncthreads();
    }
}

// ============================================================================
// Fused: even blocks = GEMM2 tiles (tensor pipe, approx spikes),
//        odd blocks  = exact fixup tiles (FMA pipe). Pipe-complementary,
//        co-resident (2 x 96 KB smem, <=256 regs/thread).
// ============================================================================
__global__ void __launch_bounds__(NT_GEMM, 2)
fused_gemm2_fixup(const float* __restrict__ sp, const float* __restrict__ w2t,
                  float* __restrict__ out,
                  const float* __restrict__ x, const float* __restrict__ W1,
                  const int* __restrict__ cnt, const int* __restrict__ list,
                  float* __restrict__ xfix)
{
    extern __shared__ float sm[];
    const int bx = blockIdx.x;
    if ((bx & 1) == 0) {
        const int tile = bx >> 1;                       // 0..511
        gemm_tile_body(sm, sp, w2t, out, (tile >> 3) * BM, (tile & 7) * BN);
    } else {
        fixup_tile_body(sm, x, W1, cnt, list, xfix, bx >> 1);  // 0..511
    }
}

// ----------------------------------------------------------------------------
// Round W1+W2 to tf32 (rna) + zero flag counters.
// ----------------------------------------------------------------------------
#define WF4   (H_DIM * H_DIM / 4)

__global__ void __launch_bounds__(256)
round_w(const float* __restrict__ W1, float* __restrict__ w1t,
        const float* __restrict__ W2, float* __restrict__ w2t,
        int* __restrict__ cnt)
{
    if (blockIdx.x == 0 && threadIdx.x < B_DIM)
        cnt[threadIdx.x] = 0;

    int gid = blockIdx.x * blockDim.x + threadIdx.x;
    const float* src = (gid < WF4) ? W1 : W2;
    float* dst = (gid < WF4) ? w1t : w2t;
    int i = (gid < WF4) ? gid : gid - WF4;

    float4 v = *(const float4*)(src + (size_t)i * 4);
    uint32_t o0, o1, o2, o3;
    asm("cvt.rna.tf32.f32 %0, %1;" : "=r"(o0) : "f"(v.x));
    asm("cvt.rna.tf32.f32 %0, %1;" : "=r"(o1) : "f"(v.y));
    asm("cvt.rna.tf32.f32 %0, %1;" : "=r"(o2) : "f"(v.z));
    asm("cvt.rna.tf32.f32 %0, %1;" : "=r"(o3) : "f"(v.w));
    float4 r;
    r.x = __uint_as_float(o0); r.y = __uint_as_float(o1);
    r.z = __uint_as_float(o2); r.w = __uint_as_float(o3);
    *(float4*)(dst + (size_t)i * 4) = r;
}

// ----------------------------------------------------------------------------
// LIF scan over approx x_proj + flag threshold-marginal lanes.
// ----------------------------------------------------------------------------
__global__ void __launch_bounds__(256)
scan_flag(const float* __restrict__ xp, float* __restrict__ spk,
          int* __restrict__ cnt, int* __restrict__ list)
{
    const int idx = blockIdx.x * blockDim.x + threadIdx.x;
    if (idx >= BH) return;

    float v = 0.0f;
    bool flag = false;
    #pragma unroll 8
    for (int t = 0; t < T_DIM; t++) {
        const float x = xp[(size_t)t * BH + idx];
        const float h = v + (x - v) * 0.5f;
        flag |= (fabsf(h - 1.0f) < DELTA);
        const bool fire = (h >= 1.0f);
        spk[(size_t)t * BH + idx] = fire ? 1.0f : 0.0f;
        v = fire ? 0.0f : h;
    }
    if (flag) {
        const int b = idx >> 10;
        const int h = idx & 1023;
        int p = atomicAdd(&cnt[b], 1);
        list[(b << 10) + p] = h;
    }
}

// ----------------------------------------------------------------------------
// fixup_diff: exact LIF per flagged lane from xfix; record spike diffs vs the
// approx spikes, bucketed per output row (t,b). No spk overwrite needed.
// ----------------------------------------------------------------------------
__global__ void __launch_bounds__(128)
fixup_diff(const float* __restrict__ xfix, const float* __restrict__ spk,
           const int* __restrict__ cnt, const int* __restrict__ list,
           int* __restrict__ rowcnt, int* __restrict__ rowdelta)
{
    const int idx = blockIdx.x * 128 + threadIdx.x;   // 64*1024
    const int b = idx >> 10;
    const int slot = idx & 1023;
    if (slot >= cnt[b]) return;

    const int h = list[(b << 10) + slot];
    const float* xc = xfix + ((size_t)(b << 10) + slot) * T_DIM;
    float v = 0.0f;
    for (int t = 0; t < T_DIM; t++) {
        const float hm = v + (xc[t] - v) * 0.5f;
        const bool fire = (hm >= 1.0f);
        const float espk = fire ? 1.0f : 0.0f;
        const float aspk = spk[(size_t)t * BH + (b << 10) + h];
        if (espk != aspk) {
            const int row = t * B_DIM + b;
            int r = atomicAdd(&rowcnt[row], 1);
            if (r < ROWCAP)
                rowdelta[(size_t)row * ROWCAP + r] = fire ? (h + 1) : -(h + 1);
        }
        v = fire ? 0.0f : hm;
    }
}

// ----------------------------------------------------------------------------
// correct_out: out[t,b,:] += sum_i sign_i * w2t[:, h_i]. Block owns one row.
// Uses tf32-rounded W2 to match the mma operand values.
// ----------------------------------------------------------------------------
__global__ void __launch_bounds__(128)
correct_out(const int* __restrict__ rowcnt, const int* __restrict__ rowdelta,
            const float* __restrict__ w2t, float* __restrict__ out)
{
    const int row = blockIdx.x;          // t*B_DIM + b
    int nc = rowcnt[row];
    if (nc == 0) return;
    if (nc > ROWCAP) nc = ROWCAP;
    const int t = row >> 6;              // /B_DIM
    const int b = row & 63;

    for (int o = threadIdx.x; o < H_DIM; o += 128) {
        float s = 0.0f;
        for (int i = 0; i < nc; i++) {
            int e = rowdelta[(size_t)row * ROWCAP + i];
            int h = (e > 0 ? e : -e) - 1;
            float w = w2t[(size_t)o * H_DIM + h];
            s += (e > 0) ? w : -w;
        }
        out[(size_t)t * BH + (b << 10) + o] += s;
    }
}

// ----------------------------------------------------------------------------
// Launch
// ----------------------------------------------------------------------------
extern "C" void kernel_launch(void* const* d_in, const int* in_sizes, int n_in,
                              void* d_out, int out_size)
{
    const float* x  = (const float*)d_in[0];  // [T,B,H]
    const float* W1 = (const float*)d_in[1];  // [H,H]
    const float* W2 = (const float*)d_in[2];  // [H,H]
    float* out = (float*)d_out;               // [T,B,H]

    float *xf, *xp, *sp, *w1t, *w2t;
    int *cnt, *list, *rowcnt, *rowdelta;
    cudaGetSymbolAddress((void**)&xf, g_xfix);
    cudaGetSymbolAddress((void**)&xp, g_xproj);
    cudaGetSymbolAddress((void**)&sp, g_spk);
    cudaGetSymbolAddress((void**)&w1t, g_w1t);
    cudaGetSymbolAddress((void**)&w2t, g_w2t);
    cudaGetSymbolAddress((void**)&cnt, g_cnt);
    cudaGetSymbolAddress((void**)&list, g_list);
    cudaGetSymbolAddress((void**)&rowcnt, g_rowcnt);
    cudaGetSymbolAddress((void**)&rowdelta, g_rowdelta);

    cudaFuncSetAttribute(gemm_tf32_mma,
                         cudaFuncAttributeMaxDynamicSharedMemorySize, SMEM_DYN);
    cudaFuncSetAttribute(fused_gemm2_fixup,
                         cudaFuncAttributeMaxDynamicSharedMemorySize, SMEM_DYN);

    // Zero per-row delta counters (32 KB).
    cudaMemsetAsync(rowcnt, 0, T_DIM * B_DIM * sizeof(int));

    // Round W1/W2 to tf32 (rna) + zero flag counters (x stays raw; HW RZ-truncates A).
    round_w<<<(2 * WF4) / 256, 256>>>(W1, w1t, W2, w2t, cnt);

    dim3 grid(H_DIM / BN, M_DIM / BM);  // (8, 64)

    // GEMM1 approx (tf32): x_proj ~= x @ W1^T
    gemm_tf32_mma<<<grid, NT_GEMM, SMEM_DYN>>>(x, w1t, xp);

    // LIF scan + flag marginal lanes (approx spikes)
    scan_flag<<<BH / 256, 256>>>(xp, sp, cnt, list);

    // FUSED: GEMM2 on approx spikes (tensor) || exact fixup GEMM (FMA)
    fused_gemm2_fixup<<<1024, NT_GEMM, SMEM_DYN>>>(sp, w2t, out,
                                                   x, W1, cnt, list, xf);

    // Exact LIF diff vs approx spikes -> per-row delta lists
    fixup_diff<<<(B_DIM * 1024) / 128, 128>>>(xf, sp, cnt, list, rowcnt, rowdelta);

    // Sparse rank-1 corrections to out
    correct_out<<<T_DIM * B_DIM, 128>>>(rowcnt, rowdelta, w2t, out);
}

// round 14
// speedup vs baseline: 1.0132x; 1.0132x over previous
#include <cuda_runtime.h>
#include <cstdint>

// Problem dims (fixed by the dataset)
#define T_DIM 128
#define B_DIM 64
#define H_DIM 1024
#define M_DIM (T_DIM * B_DIM)   // 8192
#define BH    (B_DIM * H_DIM)   // 65536

#define DELTA 1e-3f

// Scratch (allocation-free rule: __device__ globals)
__device__ float g_xfix[(size_t)B_DIM * 1024 * T_DIM]; // 32 MB exact xcol per flagged slot
__device__ float g_xproj[(size_t)M_DIM * H_DIM];       // 32 MB approx x_proj
__device__ float g_spk[(size_t)M_DIM * H_DIM];         // 32 MB spikes
__device__ float g_w1t[(size_t)H_DIM * H_DIM];         // 4 MB tf32-rounded W1
__device__ float g_w2t[(size_t)H_DIM * H_DIM];         // 4 MB tf32-rounded W2
__device__ int   g_cnt[B_DIM];
__device__ int   g_list[B_DIM * H_DIM];

// ============================================================================
// Helpers
// ============================================================================
__device__ __forceinline__ uint32_t smem_u32(const void* p) {
    uint32_t a;
    asm("{ .reg .u64 t; cvta.to.shared.u64 t, %1; cvt.u32.u64 %0, t; }"
        : "=r"(a) : "l"(p));
    return a;
}
__device__ __forceinline__ void cp_async16(uint32_t dst, const void* src) {
    asm volatile("cp.async.cg.shared.global [%0], [%1], 16;"
                 :: "r"(dst), "l"(src) : "memory");
}
#define CP_ASYNC_COMMIT() asm volatile("cp.async.commit_group;" ::: "memory")
#define CP_ASYNC_WAIT(n)  asm volatile("cp.async.wait_group %0;" :: "n"(n) : "memory")

__device__ __forceinline__ void mma_tf32(float* d, const uint32_t* a, const uint32_t* b) {
    asm volatile(
        "mma.sync.aligned.m16n8k8.row.col.f32.tf32.tf32.f32 "
        "{%0,%1,%2,%3}, {%4,%5,%6,%7}, {%8,%9}, {%0,%1,%2,%3};"
        : "+f"(d[0]), "+f"(d[1]), "+f"(d[2]), "+f"(d[3])
        : "r"(a[0]), "r"(a[1]), "r"(a[2]), "r"(a[3]),
          "r"(b[0]), "r"(b[1]));
}

// ============================================================================
// TF32 tensor-core NT-GEMM (R10/R12 best config, unchanged): C = A * B^T.
// CTA 128x128, BK=32, 128 threads, 2 CTAs/SM, 3-stage cp.async,
// XOR-swizzled smem. A may be raw fp32 (HW RZ-truncates); B pre-rounded.
// ============================================================================
#define BM        128
#define BN        128
#define BKF       32
#define A_U32     (BM * BKF)
#define B_U32     (BN * BKF)
#define STAGE_U32 (A_U32 + B_U32)
#define STAGE_BYTES (STAGE_U32 * 4)
#define NSTAGE    3
#define SMEM_DYN  (NSTAGE * STAGE_BYTES)   // 96 KB
#define NT_GEMM   128

__global__ void __launch_bounds__(NT_GEMM, 2)
gemm_tf32_mma(const float* __restrict__ A,
              const float* __restrict__ Bm,
              float* __restrict__ C)
{
    extern __shared__ float sm[];
    const uint32_t smu = smem_u32(sm);

    const int tid  = threadIdx.x;
    const int lane = tid & 31;
    const int wid  = tid >> 5;
    const int g = lane >> 2;
    const int t = lane & 3;
    const int wm = (wid >> 1) * 64;
    const int wn = (wid & 1) * 64;

    const int m0 = blockIdx.y * BM;
    const int n0 = blockIdx.x * BN;

    const float* Abase = A  + (size_t)m0 * H_DIM;
    const float* Bbase = Bm + (size_t)n0 * H_DIM;

    int lra[8], lqa[8];
    uint32_t sda[8];
#pragma unroll
    for (int p = 0; p < 8; p++) {
        int f = tid + p * NT_GEMM;
        lra[p] = f >> 3;
        lqa[p] = f & 7;
        sda[p] = (uint32_t)((lra[p] * 32 + ((lqa[p] ^ (lra[p] & 7)) << 2)) * 4);
    }

    float acc[4][8][4];
#pragma unroll
    for (int i = 0; i < 4; i++)
#pragma unroll
        for (int j = 0; j < 8; j++)
#pragma unroll
            for (int r = 0; r < 4; r++) acc[i][j][r] = 0.0f;

    auto prefetch = [&](int chunk, int stage) {
        const uint32_t base = smu + (uint32_t)stage * STAGE_BYTES;
#pragma unroll
        for (int p = 0; p < 8; p++)
            cp_async16(base + sda[p],
                       Abase + (size_t)lra[p] * H_DIM + chunk * BKF + lqa[p] * 4);
#pragma unroll
        for (int p = 0; p < 8; p++)
            cp_async16(base + (uint32_t)(A_U32 * 4) + sda[p],
                       Bbase + (size_t)lra[p] * H_DIM + chunk * BKF + lqa[p] * 4);
    };

    const int NCH = H_DIM / BKF;
    prefetch(0, 0);
    CP_ASYNC_COMMIT();
    prefetch(1, 1);
    CP_ASYNC_COMMIT();

    int stage = 0;
    for (int it = 0; it < NCH; ++it) {
        if (it + 1 < NCH) { CP_ASYNC_WAIT(1); } else { CP_ASYNC_WAIT(0); }
        __syncthreads();
        if (it + 2 < NCH) {
            int s2 = stage + 2; if (s2 >= NSTAGE) s2 -= NSTAGE;
            prefetch(it + 2, s2);
            CP_ASYNC_COMMIT();
        }

        const uint32_t* As = (const uint32_t*)sm + (size_t)stage * STAGE_U32;
        const uint32_t* Bs = As + A_U32;

#pragma unroll
        for (int ks = 0; ks < 4; ks++) {
            const int c0 = ((ks * 2) ^ g) << 2;
            const int c1 = ((ks * 2 + 1) ^ g) << 2;

            uint32_t af[4][4];
#pragma unroll
            for (int mt = 0; mt < 4; mt++) {
                const int mb = wm + mt * 16 + g;
                af[mt][0] = As[mb * 32 + c0 + t];
                af[mt][1] = As[(mb + 8) * 32 + c0 + t];
                af[mt][2] = As[mb * 32 + c1 + t];
                af[mt][3] = As[(mb + 8) * 32 + c1 + t];
            }
            uint32_t bf[8][2];
#pragma unroll
            for (int nt = 0; nt < 8; nt++) {
                const int nb = wn + nt * 8 + g;
                bf[nt][0] = Bs[nb * 32 + c0 + t];
                bf[nt][1] = Bs[nb * 32 + c1 + t];
            }
#pragma unroll
            for (int mt = 0; mt < 4; mt++)
#pragma unroll
                for (int nt = 0; nt < 8; nt++)
                    mma_tf32(acc[mt][nt], af[mt], bf[nt]);
        }

        if (++stage >= NSTAGE) stage = 0;
    }

#pragma unroll
    for (int mt = 0; mt < 4; mt++) {
#pragma unroll
        for (int nt = 0; nt < 8; nt++) {
            const int row = m0 + wm + mt * 16 + g;
            const int col = n0 + wn + nt * 8 + 2 * t;
            float2 v01 = make_float2(acc[mt][nt][0], acc[mt][nt][1]);
            float2 v23 = make_float2(acc[mt][nt][2], acc[mt][nt][3]);
            *(float2*)&C[(size_t)row * H_DIM + col] = v01;
            *(float2*)&C[(size_t)(row + 8) * H_DIM + col] = v23;
        }
    }
}

// ----------------------------------------------------------------------------
// Round W1+W2 to tf32 (rna) + zero flag counters.
// ----------------------------------------------------------------------------
#define WF4   (H_DIM * H_DIM / 4)

__global__ void __launch_bounds__(256)
round_w(const float* __restrict__ W1, float* __restrict__ w1t,
        const float* __restrict__ W2, float* __restrict__ w2t,
        int* __restrict__ cnt)
{
    if (blockIdx.x == 0 && threadIdx.x < B_DIM)
        cnt[threadIdx.x] = 0;

    int gid = blockIdx.x * blockDim.x + threadIdx.x;
    const float* src = (gid < WF4) ? W1 : W2;
    float* dst = (gid < WF4) ? w1t : w2t;
    int i = (gid < WF4) ? gid : gid - WF4;

    float4 v = *(const float4*)(src + (size_t)i * 4);
    uint32_t o0, o1, o2, o3;
    asm("cvt.rna.tf32.f32 %0, %1;" : "=r"(o0) : "f"(v.x));
    asm("cvt.rna.tf32.f32 %0, %1;" : "=r"(o1) : "f"(v.y));
    asm("cvt.rna.tf32.f32 %0, %1;" : "=r"(o2) : "f"(v.z));
    asm("cvt.rna.tf32.f32 %0, %1;" : "=r"(o3) : "f"(v.w));
    float4 r;
    r.x = __uint_as_float(o0); r.y = __uint_as_float(o1);
    r.z = __uint_as_float(o2); r.w = __uint_as_float(o3);
    *(float4*)(dst + (size_t)i * 4) = r;
}

// ----------------------------------------------------------------------------
// LIF scan (vectorized: one thread owns 4 adjacent h lanes, float4 I/O)
// + flag threshold-marginal lanes.
// ----------------------------------------------------------------------------
__global__ void __launch_bounds__(256)
scan_flag(const float* __restrict__ xp, float* __restrict__ spk,
          int* __restrict__ cnt, int* __restrict__ list)
{
    const int i4 = blockIdx.x * blockDim.x + threadIdx.x;   // float4 lane group
    if (i4 >= BH / 4) return;

    const float4* xp4 = (const float4*)xp;
    float4* spk4 = (float4*)spk;

    float4 v = make_float4(0.f, 0.f, 0.f, 0.f);
    int flags = 0;
    #pragma unroll 4
    for (int t = 0; t < T_DIM; t++) {
        float4 xv = xp4[(size_t)t * (BH / 4) + i4];
        float4 h;
        h.x = v.x + (xv.x - v.x) * 0.5f;
        h.y = v.y + (xv.y - v.y) * 0.5f;
        h.z = v.z + (xv.z - v.z) * 0.5f;
        h.w = v.w + (xv.w - v.w) * 0.5f;
        flags |= (fabsf(h.x - 1.0f) < DELTA) ? 1 : 0;
        flags |= (fabsf(h.y - 1.0f) < DELTA) ? 2 : 0;
        flags |= (fabsf(h.z - 1.0f) < DELTA) ? 4 : 0;
        flags |= (fabsf(h.w - 1.0f) < DELTA) ? 8 : 0;
        float4 s;
        s.x = (h.x >= 1.0f) ? 1.0f : 0.0f;
        s.y = (h.y >= 1.0f) ? 1.0f : 0.0f;
        s.z = (h.z >= 1.0f) ? 1.0f : 0.0f;
        s.w = (h.w >= 1.0f) ? 1.0f : 0.0f;
        spk4[(size_t)t * (BH / 4) + i4] = s;
        v.x = (h.x >= 1.0f) ? 0.0f : h.x;
        v.y = (h.y >= 1.0f) ? 0.0f : h.y;
        v.z = (h.z >= 1.0f) ? 0.0f : h.z;
        v.w = (h.w >= 1.0f) ? 0.0f : h.w;
    }
    if (flags) {
        const int idx0 = i4 * 4;
        const int b = idx0 >> 10;
        #pragma unroll
        for (int c = 0; c < 4; c++) {
            if (flags & (1 << c)) {
                int p = atomicAdd(&cnt[b], 1);
                list[(b << 10) + p] = (idx0 + c) & 1023;
            }
        }
    }
}

// ----------------------------------------------------------------------------
// fixup_gemm v3: exact fp32 x_proj columns for flagged lanes -> g_xfix.
// Grid (B_DIM, 4): y&1 = t-half, y>>1 = h-slice (batches of 64, stride 128).
// 256 threads, CTA tile 64h x 64t, thread tile 4j x 4t
//   (jg = tid&15 -> j = jg + 16*jj; tg = tid>>4 -> t = t0 + 4*tg + tt).
// XOR-block swizzle: row r: phys = r*64 + ((kq ^ (r&15))<<2) + (k&3)
//   -> conflict-free float4 STS/LDS; xv loads broadcast (2 rows per warp).
// Per thread-kg: 8 LDS.128 per 64 FMA (0.5 floats/FMA).
// ----------------------------------------------------------------------------
__global__ void __launch_bounds__(256)
fixup_gemm(const float* __restrict__ x,   // fp32 x [T,B,H]
           const float* __restrict__ W1,  // fp32 W1 [H,H]
           const int* __restrict__ cnt,
           const int* __restrict__ list,
           float* __restrict__ xfix)      // [b][slot<1024][t]
{
    __shared__ float Xs[64 * 64];   // 16 KB (t rows, swizzled k)
    __shared__ float Ws[64 * 64];   // 16 KB (j rows, swizzled k)
    __shared__ int   hlist[64];

    const int b   = blockIdx.x;
    const int th  = blockIdx.y & 1;       // t half
    const int hs  = blockIdx.y >> 1;      // h slice (0..1)
    const int tid = threadIdx.x;
    const int jg  = tid & 15;             // j = jg + 16*jj
    const int tg  = tid >> 4;             // 0..15, t = t0 + 4*tg + tt
    const int n   = cnt[b];
    const int boff = b << 10;
    const int t0 = th * 64;

    for (int base = hs * 64; base < n; base += 128) {
        if (tid < 64)
            hlist[tid] = (base + tid < n) ? list[boff + base + tid] : 0;
        __syncthreads();

        float acc[4][4];
#pragma unroll
        for (int jj = 0; jj < 4; jj++)
#pragma unroll
            for (int tt = 0; tt < 4; tt++) acc[jj][tt] = 0.0f;

        for (int kc = 0; kc < 16; kc++) {
            // Xs: 64 t x 64 k = 1024 f4, 4/thread (coalesced 256 B rows)
#pragma unroll
            for (int p = 0; p < 4; p++) {
                int f = tid + p * 256;
                int tl = f >> 4, kq = f & 15;
                float4 v = *(const float4*)(x + (size_t)(t0 + tl) * BH
                                            + boff + kc * 64 + kq * 4);
                *(float4*)&Xs[tl * 64 + ((kq ^ (tl & 15)) << 2)] = v;
            }
            // Ws: 64 j x 64 k = 1024 f4, 4/thread
#pragma unroll
            for (int p = 0; p < 4; p++) {
                int f = tid + p * 256;
                int j = f >> 4, kq = f & 15;
                float4 v = *(const float4*)(W1 + (size_t)hlist[j] * H_DIM
                                            + kc * 64 + kq * 4);
                *(float4*)&Ws[j * 64 + ((kq ^ (j & 15)) << 2)] = v;
            }
            __syncthreads();

            // Exact fp32, k-sequential per accumulator
#pragma unroll
            for (int kg = 0; kg < 16; kg++) {
                float4 wv[4];
#pragma unroll
                for (int jj = 0; jj < 4; jj++) {
                    int j = jg + 16 * jj;                 // j&15 == jg
                    wv[jj] = *(const float4*)&Ws[j * 64 + ((kg ^ jg) << 2)];
                }
                float4 xv[4];
#pragma unroll
                for (int tt = 0; tt < 4; tt++) {
                    int r = 4 * tg + tt;
                    xv[tt] = *(const float4*)&Xs[r * 64 + ((kg ^ (r & 15)) << 2)];
                }
#pragma unroll
                for (int jj = 0; jj < 4; jj++)
#pragma unroll
                    for (int tt = 0; tt < 4; tt++) {
                        acc[jj][tt] = fmaf(wv[jj].x, xv[tt].x, acc[jj][tt]);
                        acc[jj][tt] = fmaf(wv[jj].y, xv[tt].y, acc[jj][tt]);
                        acc[jj][tt] = fmaf(wv[jj].z, xv[tt].z, acc[jj][tt]);
                        acc[jj][tt] = fmaf(wv[jj].w, xv[tt].w, acc[jj][tt]);
                    }
            }
            __syncthreads();
        }

        // Write exact columns: xfix[(boff + base + j) * T_DIM + t0 + 4*tg + tt]
#pragma unroll
        for (int jj = 0; jj < 4; jj++) {
            int slot = base + jg + 16 * jj;
            float4 v = make_float4(acc[jj][0], acc[jj][1], acc[jj][2], acc[jj][3]);
            *(float4*)&xfix[((size_t)boff + slot) * T_DIM + t0 + 4 * tg] = v;
        }
        __syncthreads();
    }
}

// ----------------------------------------------------------------------------
// fixup_lif: rerun exact LIF for flagged lanes from g_xfix, overwrite spikes.
// ----------------------------------------------------------------------------
__global__ void __launch_bounds__(256)
fixup_lif(const float* __restrict__ xfix,
          const int* __restrict__ cnt,
          const int* __restrict__ list,
          float* __restrict__ spk)
{
    const int idx = blockIdx.x * blockDim.x + threadIdx.x;  // 64*1024 lanes
    const int b = idx >> 10;
    const int slot = idx & 1023;
    if (b >= B_DIM || slot >= cnt[b]) return;

    const int h = list[(b << 10) + slot];
    const float* xc = xfix + ((size_t)(b << 10) + slot) * T_DIM;
    float v = 0.0f;
    for (int t = 0; t < T_DIM; t++) {
        const float hm = v + (xc[t] - v) * 0.5f;
        const bool fire = (hm >= 1.0f);
        spk[(size_t)t * BH + (b << 10) + h] = fire ? 1.0f : 0.0f;
        v = fire ? 0.0f : hm;
    }
}

// ----------------------------------------------------------------------------
// Launch
// ----------------------------------------------------------------------------
extern "C" void kernel_launch(void* const* d_in, const int* in_sizes, int n_in,
                              void* d_out, int out_size)
{
    const float* x  = (const float*)d_in[0];  // [T,B,H]
    const float* W1 = (const float*)d_in[1];  // [H,H]
    const float* W2 = (const float*)d_in[2];  // [H,H]
    float* out = (float*)d_out;               // [T,B,H]

    float *xf, *xp, *sp, *w1t, *w2t;
    int *cnt, *list;
    cudaGetSymbolAddress((void**)&xf, g_xfix);
    cudaGetSymbolAddress((void**)&xp, g_xproj);
    cudaGetSymbolAddress((void**)&sp, g_spk);
    cudaGetSymbolAddress((void**)&w1t, g_w1t);
    cudaGetSymbolAddress((void**)&w2t, g_w2t);
    cudaGetSymbolAddress((void**)&cnt, g_cnt);
    cudaGetSymbolAddress((void**)&list, g_list);

    cudaFuncSetAttribute(gemm_tf32_mma,
                         cudaFuncAttributeMaxDynamicSharedMemorySize, SMEM_DYN);

    // Round W1/W2 to tf32 (rna) + zero counters (x stays raw; HW RZ-truncates A).
    round_w<<<(2 * WF4) / 256, 256>>>(W1, w1t, W2, w2t, cnt);

    dim3 grid(H_DIM / BN, M_DIM / BM);  // (8, 64)

    // GEMM1 approx (tf32): x_proj ~= x @ W1^T
    gemm_tf32_mma<<<grid, NT_GEMM, SMEM_DYN>>>(x, w1t, xp);

    // LIF scan + flag marginal lanes
    scan_flag<<<(BH / 4) / 256, 256>>>(xp, sp, cnt, list);

    // Exact fp32 recompute of flagged columns, then exact LIF rerun
    fixup_gemm<<<dim3(B_DIM, 4), 256>>>(x, W1, cnt, list, xf);
    fixup_lif<<<(B_DIM * 1024) / 256, 256>>>(xf, cnt, list, sp);

    // GEMM2 (tf32): out = spikes @ W2^T
    gemm_tf32_mma<<<grid, NT_GEMM, SMEM_DYN>>>(sp, w2t, out);
}

// round 16
// speedup vs baseline: 1.0669x; 1.0530x over previous
#include <cuda_runtime.h>
#include <cuda_bf16.h>
#include <cstdint>

// Problem dims (fixed by the dataset)
#define T_DIM 128
#define B_DIM 64
#define H_DIM 1024
#define M_DIM (T_DIM * B_DIM)   // 8192
#define BH    (B_DIM * H_DIM)   // 65536

#define DELTA 1e-3f

// Scratch (allocation-free rule: __device__ globals)
__device__ float    g_xfix[(size_t)B_DIM * 1024 * T_DIM]; // 32 MB exact xcol per flagged slot
__device__ float    g_xproj[(size_t)M_DIM * H_DIM];       // 32 MB approx x_proj
__device__ uint16_t g_spk[(size_t)M_DIM * H_DIM];         // 16 MB spikes (bf16)
__device__ float    g_w1t[(size_t)H_DIM * H_DIM];         // 4 MB tf32-rounded W1
__device__ uint16_t g_w2h[(size_t)H_DIM * H_DIM];         // 2 MB bf16 hi(W2)
__device__ uint16_t g_w2l[(size_t)H_DIM * H_DIM];         // 2 MB bf16 lo(W2)
__device__ int      g_cnt[B_DIM];
__device__ int      g_list[B_DIM * H_DIM];

#define BF16_ONE  0x3F80u
#define BF16_ZERO 0x0000u

// ============================================================================
// Helpers
// ============================================================================
__device__ __forceinline__ uint32_t smem_u32(const void* p) {
    uint32_t a;
    asm("{ .reg .u64 t; cvta.to.shared.u64 t, %1; cvt.u32.u64 %0, t; }"
        : "=r"(a) : "l"(p));
    return a;
}
__device__ __forceinline__ void cp_async16(uint32_t dst, const void* src) {
    asm volatile("cp.async.cg.shared.global [%0], [%1], 16;"
                 :: "r"(dst), "l"(src) : "memory");
}
#define CP_ASYNC_COMMIT() asm volatile("cp.async.commit_group;" ::: "memory")
#define CP_ASYNC_WAIT(n)  asm volatile("cp.async.wait_group %0;" :: "n"(n) : "memory")

__device__ __forceinline__ void mma_tf32(float* d, const uint32_t* a, const uint32_t* b) {
    asm volatile(
        "mma.sync.aligned.m16n8k8.row.col.f32.tf32.tf32.f32 "
        "{%0,%1,%2,%3}, {%4,%5,%6,%7}, {%8,%9}, {%0,%1,%2,%3};"
        : "+f"(d[0]), "+f"(d[1]), "+f"(d[2]), "+f"(d[3])
        : "r"(a[0]), "r"(a[1]), "r"(a[2]), "r"(a[3]),
          "r"(b[0]), "r"(b[1]));
}
__device__ __forceinline__ void mma_bf16(float* d, const uint32_t* a, const uint32_t* b) {
    asm volatile(
        "mma.sync.aligned.m16n8k16.row.col.f32.bf16.bf16.f32 "
        "{%0,%1,%2,%3}, {%4,%5,%6,%7}, {%8,%9}, {%0,%1,%2,%3};"
        : "+f"(d[0]), "+f"(d[1]), "+f"(d[2]), "+f"(d[3])
        : "r"(a[0]), "r"(a[1]), "r"(a[2]), "r"(a[3]),
          "r"(b[0]), "r"(b[1]));
}

// ============================================================================
// GEMM1: TF32 tensor-core NT-GEMM (R12-verbatim): C = A * B^T.
// CTA 128x128, BK=32, 128 threads, 2 CTAs/SM, 3-stage cp.async.
// A = raw fp32 x (HW RZ-truncates); B = tf32-rounded W1.
// ============================================================================
#define BM        128
#define BN        128
#define BKF       32
#define A_U32     (BM * BKF)
#define B_U32     (BN * BKF)
#define STAGE_U32 (A_U32 + B_U32)
#define STAGE_BYTES (STAGE_U32 * 4)
#define NSTAGE    3
#define SMEM_DYN  (NSTAGE * STAGE_BYTES)   // 96 KB
#define NT_GEMM   128

__global__ void __launch_bounds__(NT_GEMM, 2)
gemm_tf32_mma(const float* __restrict__ A,
              const float* __restrict__ Bm,
              float* __restrict__ C)
{
    extern __shared__ float sm[];
    const uint32_t smu = smem_u32(sm);

    const int tid  = threadIdx.x;
    const int lane = tid & 31;
    const int wid  = tid >> 5;
    const int g = lane >> 2;
    const int t = lane & 3;
    const int wm = (wid >> 1) * 64;
    const int wn = (wid & 1) * 64;

    const int m0 = blockIdx.y * BM;
    const int n0 = blockIdx.x * BN;

    const float* Abase = A  + (size_t)m0 * H_DIM;
    const float* Bbase = Bm + (size_t)n0 * H_DIM;

    int lra[8], lqa[8];
    uint32_t sda[8];
#pragma unroll
    for (int p = 0; p < 8; p++) {
        int f = tid + p * NT_GEMM;
        lra[p] = f >> 3;
        lqa[p] = f & 7;
        sda[p] = (uint32_t)((lra[p] * 32 + ((lqa[p] ^ (lra[p] & 7)) << 2)) * 4);
    }

    float acc[4][8][4];
#pragma unroll
    for (int i = 0; i < 4; i++)
#pragma unroll
        for (int j = 0; j < 8; j++)
#pragma unroll
            for (int r = 0; r < 4; r++) acc[i][j][r] = 0.0f;

    auto prefetch = [&](int chunk, int stage) {
        const uint32_t base = smu + (uint32_t)stage * STAGE_BYTES;
#pragma unroll
        for (int p = 0; p < 8; p++)
            cp_async16(base + sda[p],
                       Abase + (size_t)lra[p] * H_DIM + chunk * BKF + lqa[p] * 4);
#pragma unroll
        for (int p = 0; p < 8; p++)
            cp_async16(base + (uint32_t)(A_U32 * 4) + sda[p],
                       Bbase + (size_t)lra[p] * H_DIM + chunk * BKF + lqa[p] * 4);
    };

    const int NCH = H_DIM / BKF;
    prefetch(0, 0);
    CP_ASYNC_COMMIT();
    prefetch(1, 1);
    CP_ASYNC_COMMIT();

    int stage = 0;
    for (int it = 0; it < NCH; ++it) {
        if (it + 1 < NCH) { CP_ASYNC_WAIT(1); } else { CP_ASYNC_WAIT(0); }
        __syncthreads();
        if (it + 2 < NCH) {
            int s2 = stage + 2; if (s2 >= NSTAGE) s2 -= NSTAGE;
            prefetch(it + 2, s2);
            CP_ASYNC_COMMIT();
        }

        const uint32_t* As = (const uint32_t*)sm + (size_t)stage * STAGE_U32;
        const uint32_t* Bs = As + A_U32;

#pragma unroll
        for (int ks = 0; ks < 4; ks++) {
            const int c0 = ((ks * 2) ^ g) << 2;
            const int c1 = ((ks * 2 + 1) ^ g) << 2;

            uint32_t af[4][4];
#pragma unroll
            for (int mt = 0; mt < 4; mt++) {
                const int mb = wm + mt * 16 + g;
                af[mt][0] = As[mb * 32 + c0 + t];
                af[mt][1] = As[(mb + 8) * 32 + c0 + t];
                af[mt][2] = As[mb * 32 + c1 + t];
                af[mt][3] = As[(mb + 8) * 32 + c1 + t];
            }
            uint32_t bf[8][2];
#pragma unroll
            for (int nt = 0; nt < 8; nt++) {
                const int nb = wn + nt * 8 + g;
                bf[nt][0] = Bs[nb * 32 + c0 + t];
                bf[nt][1] = Bs[nb * 32 + c1 + t];
            }
#pragma unroll
            for (int mt = 0; mt < 4; mt++)
#pragma unroll
                for (int nt = 0; nt < 8; nt++)
                    mma_tf32(acc[mt][nt], af[mt], bf[nt]);
        }

        if (++stage >= NSTAGE) stage = 0;
    }

#pragma unroll
    for (int mt = 0; mt < 4; mt++) {
#pragma unroll
        for (int nt = 0; nt < 8; nt++) {
            const int row = m0 + wm + mt * 16 + g;
            const int col = n0 + wn + nt * 8 + 2 * t;
            float2 v01 = make_float2(acc[mt][nt][0], acc[mt][nt][1]);
            float2 v23 = make_float2(acc[mt][nt][2], acc[mt][nt][3]);
            *(float2*)&C[(size_t)row * H_DIM + col] = v01;
            *(float2*)&C[(size_t)(row + 8) * H_DIM + col] = v23;
        }
    }
}

// ============================================================================
// GEMM2: bf16 2-term split NT-GEMM: out = spk @ (W2_hi + W2_lo)^T.
// spk exactly representable in bf16; W2 = hi + lo (both bf16).
// CTA 128x128, BK=64 (128 B rows, same XOR swizzle), 128 threads,
// 2-stage cp.async (48 KB/stage -> 96 KB), 2 CTAs/SM.
// Per k16 step: 16 A + 16 Bh + 16 Bl LDS.32, 64 MMAs (hi+lo into one acc).
// ============================================================================
#define BK2        64
#define A2_BYTES   (128 * BK2 * 2)          // 16 KB
#define STAGE2_BYTES (3 * A2_BYTES)         // 48 KB
#define SMEM2_DYN  (2 * STAGE2_BYTES)       // 96 KB

__global__ void __launch_bounds__(128, 2)
gemm_bf16_split(const uint16_t* __restrict__ Asp,  // spikes bf16 [M, K]
                const uint16_t* __restrict__ Bh,   // W2 hi bf16 [N, K]
                const uint16_t* __restrict__ Bl,   // W2 lo bf16 [N, K]
                float* __restrict__ C)
{
    extern __shared__ char smc[];
    const uint32_t smu = smem_u32(smc);

    const int tid  = threadIdx.x;
    const int lane = tid & 31;
    const int wid  = tid >> 5;
    const int g = lane >> 2;
    const int t = lane & 3;
    const int wm = (wid >> 1) * 64;
    const int wn = (wid & 1) * 64;

    const int m0 = blockIdx.y * BM;
    const int n0 = blockIdx.x * BN;

    // cp.async geometry: each operand tile = 1024 16B-chunks / 128 thr = 8.
    int lra[8], lqa[8];
    uint32_t sda[8];
#pragma unroll
    for (int p = 0; p < 8; p++) {
        int f = tid + p * 128;
        lra[p] = f >> 3;           // row 0..127
        lqa[p] = f & 7;            // 16B chunk 0..7
        sda[p] = (uint32_t)(lra[p] * 128 + ((lqa[p] ^ (lra[p] & 7)) << 4));
    }

    float acc[4][8][4];
#pragma unroll
    for (int i = 0; i < 4; i++)
#pragma unroll
        for (int j = 0; j < 8; j++)
#pragma unroll
            for (int r = 0; r < 4; r++) acc[i][j][r] = 0.0f;

    auto prefetch = [&](int chunk, int stage) {
        const uint32_t base = smu + (uint32_t)stage * STAGE2_BYTES;
#pragma unroll
        for (int p = 0; p < 8; p++)
            cp_async16(base + sda[p],
                       Asp + ((size_t)(m0 + lra[p]) * H_DIM + chunk * BK2 + lqa[p] * 8));
#pragma unroll
        for (int p = 0; p < 8; p++)
            cp_async16(base + (uint32_t)A2_BYTES + sda[p],
                       Bh + ((size_t)(n0 + lra[p]) * H_DIM + chunk * BK2 + lqa[p] * 8));
#pragma unroll
        for (int p = 0; p < 8; p++)
            cp_async16(base + (uint32_t)(2 * A2_BYTES) + sda[p],
                       Bl + ((size_t)(n0 + lra[p]) * H_DIM + chunk * BK2 + lqa[p] * 8));
    };

    const int NCH = H_DIM / BK2;   // 16
    prefetch(0, 0);
    CP_ASYNC_COMMIT();

    int buf = 0;
    for (int it = 0; it < NCH; ++it) {
        CP_ASYNC_WAIT(0);
        __syncthreads();
        if (it + 1 < NCH) {
            prefetch(it + 1, buf ^ 1);
            CP_ASYNC_COMMIT();
        }

        // Row stride = 128 B = 32 words.
        const uint32_t* As  = (const uint32_t*)(smc + (size_t)buf * STAGE2_BYTES);
        const uint32_t* Bhs = As + A2_BYTES / 4;
        const uint32_t* Bls = Bhs + A2_BYTES / 4;

#pragma unroll
        for (int ks = 0; ks < 4; ks++) {
            uint32_t af[4][4];
#pragma unroll
            for (int mt = 0; mt < 4; mt++) {
                const int rb = wm + mt * 16 + g;
                const int c0 = ((2 * ks) ^ (rb & 7)) * 4 + t;
                const int c1 = ((2 * ks + 1) ^ (rb & 7)) * 4 + t;
                af[mt][0] = As[rb * 32 + c0];          // row g,   k 2t,2t+1
                af[mt][1] = As[(rb + 8) * 32 + c0];    // row g+8, k 2t,2t+1
                af[mt][2] = As[rb * 32 + c1];          // row g,   k 2t+8,2t+9
                af[mt][3] = As[(rb + 8) * 32 + c1];    // row g+8, k 2t+8,2t+9
            }
            uint32_t bh[8][2], bl[8][2];
#pragma unroll
            for (int nt = 0; nt < 8; nt++) {
                const int rn = wn + nt * 8 + g;
                const int d0 = rn * 32 + ((2 * ks) ^ (rn & 7)) * 4 + t;
                const int d1 = rn * 32 + ((2 * ks + 1) ^ (rn & 7)) * 4 + t;
                bh[nt][0] = Bhs[d0];
                bh[nt][1] = Bhs[d1];
                bl[nt][0] = Bls[d0];
                bl[nt][1] = Bls[d1];
            }
#pragma unroll
            for (int mt = 0; mt < 4; mt++)
#pragma unroll
                for (int nt = 0; nt < 8; nt++) {
                    mma_bf16(acc[mt][nt], af[mt], bh[nt]);
                    mma_bf16(acc[mt][nt], af[mt], bl[nt]);
                }
        }
        __syncthreads();
        buf ^= 1;
    }

#pragma unroll
    for (int mt = 0; mt < 4; mt++) {
#pragma unroll
        for (int nt = 0; nt < 8; nt++) {
            const int row = m0 + wm + mt * 16 + g;
            const int col = n0 + wn + nt * 8 + 2 * t;
            float2 v01 = make_float2(acc[mt][nt][0], acc[mt][nt][1]);
            float2 v23 = make_float2(acc[mt][nt][2], acc[mt][nt][3]);
            *(float2*)&C[(size_t)row * H_DIM + col] = v01;
            *(float2*)&C[(size_t)(row + 8) * H_DIM + col] = v23;
        }
    }
}

// ----------------------------------------------------------------------------
// round_w: W1 -> tf32 (rna); W2 -> bf16 hi + bf16 lo. Zeroes flag counters.
// ----------------------------------------------------------------------------
#define WF4   (H_DIM * H_DIM / 4)          // 262144

__global__ void __launch_bounds__(256)
round_w(const float* __restrict__ W1, float* __restrict__ w1t,
        const float* __restrict__ W2, uint16_t* __restrict__ w2h,
        uint16_t* __restrict__ w2l, int* __restrict__ cnt)
{
    if (blockIdx.x == 0 && threadIdx.x < B_DIM)
        cnt[threadIdx.x] = 0;

    int gid = blockIdx.x * blockDim.x + threadIdx.x;
    if (gid < WF4) {
        float4 v = *(const float4*)(W1 + (size_t)gid * 4);
        uint32_t o0, o1, o2, o3;
        asm("cvt.rna.tf32.f32 %0, %1;" : "=r"(o0) : "f"(v.x));
        asm("cvt.rna.tf32.f32 %0, %1;" : "=r"(o1) : "f"(v.y));
        asm("cvt.rna.tf32.f32 %0, %1;" : "=r"(o2) : "f"(v.z));
        asm("cvt.rna.tf32.f32 %0, %1;" : "=r"(o3) : "f"(v.w));
        float4 r;
        r.x = __uint_as_float(o0); r.y = __uint_as_float(o1);
        r.z = __uint_as_float(o2); r.w = __uint_as_float(o3);
        *(float4*)(w1t + (size_t)gid * 4) = r;
    } else {
        int i = gid - WF4;
        float4 v = *(const float4*)(W2 + (size_t)i * 4);
        float w[4] = {v.x, v.y, v.z, v.w};
        uint16_t hi[4], lo[4];
#pragma unroll
        for (int c = 0; c < 4; c++) {
            __nv_bfloat16 h = __float2bfloat16_rn(w[c]);
            float rem = w[c] - __bfloat162float(h);
            __nv_bfloat16 l = __float2bfloat16_rn(rem);
            hi[c] = __bfloat16_as_ushort(h);
            lo[c] = __bfloat16_as_ushort(l);
        }
        uint2 ho, loo;
        ho.x  = (uint32_t)hi[0] | ((uint32_t)hi[1] << 16);
        ho.y  = (uint32_t)hi[2] | ((uint32_t)hi[3] << 16);
        loo.x = (uint32_t)lo[0] | ((uint32_t)lo[1] << 16);
        loo.y = (uint32_t)lo[2] | ((uint32_t)lo[3] << 16);
        *(uint2*)(w2h + (size_t)i * 4) = ho;
        *(uint2*)(w2l + (size_t)i * 4) = loo;
    }
}

// ----------------------------------------------------------------------------
// LIF scan (vectorized float4 reads, bf16 spike writes) + flag marginal lanes.
// ----------------------------------------------------------------------------
__global__ void __launch_bounds__(256)
scan_flag(const float* __restrict__ xp, uint16_t* __restrict__ spk,
          int* __restrict__ cnt, int* __restrict__ list)
{
    const int i4 = blockIdx.x * blockDim.x + threadIdx.x;
    if (i4 >= BH / 4) return;

    const float4* xp4 = (const float4*)xp;
    uint2* spk4 = (uint2*)spk;

    float4 v = make_float4(0.f, 0.f, 0.f, 0.f);
    int flags = 0;
    #pragma unroll 4
    for (int t = 0; t < T_DIM; t++) {
        float4 xv = xp4[(size_t)t * (BH / 4) + i4];
        float4 h;
        h.x = v.x + (xv.x - v.x) * 0.5f;
        h.y = v.y + (xv.y - v.y) * 0.5f;
        h.z = v.z + (xv.z - v.z) * 0.5f;
        h.w = v.w + (xv.w - v.w) * 0.5f;
        flags |= (fabsf(h.x - 1.0f) < DELTA) ? 1 : 0;
        flags |= (fabsf(h.y - 1.0f) < DELTA) ? 2 : 0;
        flags |= (fabsf(h.z - 1.0f) < DELTA) ? 4 : 0;
        flags |= (fabsf(h.w - 1.0f) < DELTA) ? 8 : 0;
        uint32_t s0 = (h.x >= 1.0f) ? BF16_ONE : BF16_ZERO;
        uint32_t s1 = (h.y >= 1.0f) ? BF16_ONE : BF16_ZERO;
        uint32_t s2 = (h.z >= 1.0f) ? BF16_ONE : BF16_ZERO;
        uint32_t s3 = (h.w >= 1.0f) ? BF16_ONE : BF16_ZERO;
        uint2 o;
        o.x = s0 | (s1 << 16);
        o.y = s2 | (s3 << 16);
        spk4[(size_t)t * (BH / 4) + i4] = o;
        v.x = (h.x >= 1.0f) ? 0.0f : h.x;
        v.y = (h.y >= 1.0f) ? 0.0f : h.y;
        v.z = (h.z >= 1.0f) ? 0.0f : h.z;
        v.w = (h.w >= 1.0f) ? 0.0f : h.w;
    }
    if (flags) {
        const int idx0 = i4 * 4;
        const int b = idx0 >> 10;
        #pragma unroll
        for (int c = 0; c < 4; c++) {
            if (flags & (1 << c)) {
                int p = atomicAdd(&cnt[b], 1);
                list[(b << 10) + p] = (idx0 + c) & 1023;
            }
        }
    }
}

// ----------------------------------------------------------------------------
// fixup_gemm (R12-verbatim, the 61.7us version): exact fp32 x_proj columns
// for flagged lanes -> g_xfix. Grid (B_DIM, 8): y&3 = h-slice, y>>2 = t-half.
// ----------------------------------------------------------------------------
__global__ void __launch_bounds__(256)
fixup_gemm(const float* __restrict__ x,
           const float* __restrict__ W1,
           const int* __restrict__ cnt,
           const int* __restrict__ list,
           float* __restrict__ xfix)
{
    __shared__ float Xs[64 * 64];   // 16 KB
    __shared__ float Ws[32 * 64];   //  8 KB
    __shared__ int   hlist[32];

    const int b   = blockIdx.x;
    const int hs  = blockIdx.y & 3;
    const int th  = blockIdx.y >> 2;
    const int tid = threadIdx.x;
    const int jg  = tid & 15;
    const int tg  = tid >> 4;
    const int n   = cnt[b];

    const int boff = b << 10;
    const int tglob0 = th * 64;

    for (int base = hs * 32; base < n; base += 128) {
        if (tid < 32)
            hlist[tid] = (base + tid < n) ? list[boff + base + tid] : 0;
        __syncthreads();

        float acc[2][4];
#pragma unroll
        for (int jj = 0; jj < 2; jj++)
#pragma unroll
            for (int tt = 0; tt < 4; tt++) acc[jj][tt] = 0.0f;

        for (int kc = 0; kc < 16; kc++) {
#pragma unroll
            for (int p = 0; p < 4; p++) {
                int f = tid + p * 256;
                int tl = f >> 4, kq = f & 15;
                float4 v = *(const float4*)(x + (size_t)(tglob0 + tl) * BH
                                            + boff + kc * 64 + kq * 4);
                *(float4*)&Xs[tl * 64 + ((kq ^ (tl & 15)) << 2)] = v;
            }
#pragma unroll
            for (int p = 0; p < 2; p++) {
                int f = tid + p * 256;
                int j = f >> 4, kq = f & 15;
                float4 v = *(const float4*)(W1 + (size_t)hlist[j] * H_DIM
                                            + kc * 64 + kq * 4);
                *(float4*)&Ws[j * 64 + ((kq ^ (j & 15)) << 2)] = v;
            }
            __syncthreads();

#pragma unroll
            for (int kg = 0; kg < 16; kg++) {
                float4 wv0 = *(const float4*)&Ws[jg * 64 + ((kg ^ (jg & 15)) << 2)];
                float4 wv1 = *(const float4*)&Ws[(jg + 16) * 64 + ((kg ^ ((jg + 16) & 15)) << 2)];
                float4 xv[4];
#pragma unroll
                for (int tt = 0; tt < 4; tt++) {
                    int r = 4 * tg + tt;
                    xv[tt] = *(const float4*)&Xs[r * 64 + ((kg ^ (r & 15)) << 2)];
                }
#pragma unroll
                for (int tt = 0; tt < 4; tt++) {
                    acc[0][tt] = fmaf(wv0.x, xv[tt].x, acc[0][tt]);
                    acc[0][tt] = fmaf(wv0.y, xv[tt].y, acc[0][tt]);
                    acc[0][tt] = fmaf(wv0.z, xv[tt].z, acc[0][tt]);
                    acc[0][tt] = fmaf(wv0.w, xv[tt].w, acc[0][tt]);
                    acc[1][tt] = fmaf(wv1.x, xv[tt].x, acc[1][tt]);
                    acc[1][tt] = fmaf(wv1.y, xv[tt].y, acc[1][tt]);
                    acc[1][tt] = fmaf(wv1.z, xv[tt].z, acc[1][tt]);
                    acc[1][tt] = fmaf(wv1.w, xv[tt].w, acc[1][tt]);
                }
            }
            __syncthreads();
        }

#pragma unroll
        for (int jj = 0; jj < 2; jj++) {
            int slot = base + jg + 16 * jj;
            float4 v = make_float4(acc[jj][0], acc[jj][1], acc[jj][2], acc[jj][3]);
            *(float4*)&xfix[((size_t)boff + slot) * T_DIM + tglob0 + 4 * tg] = v;
        }
        __syncthreads();
    }
}

// ----------------------------------------------------------------------------
// fixup_lif: rerun exact LIF for flagged lanes, overwrite bf16 spikes.
// ----------------------------------------------------------------------------
__global__ void __launch_bounds__(256)
fixup_lif(const float* __restrict__ xfix,
          const int* __restrict__ cnt,
          const int* __restrict__ list,
          uint16_t* __restrict__ spk)
{
    const int idx = blockIdx.x * blockDim.x + threadIdx.x;
    const int b = idx >> 10;
    const int slot = idx & 1023;
    if (b >= B_DIM || slot >= cnt[b]) return;

    const int h = list[(b << 10) + slot];
    const float* xc = xfix + ((size_t)(b << 10) + slot) * T_DIM;
    float v = 0.0f;
    for (int t = 0; t < T_DIM; t++) {
        const float hm = v + (xc[t] - v) * 0.5f;
        const bool fire = (hm >= 1.0f);
        spk[(size_t)t * BH + (b << 10) + h] = fire ? (uint16_t)BF16_ONE
                                                   : (uint16_t)BF16_ZERO;
        v = fire ? 0.0f : hm;
    }
}

// ----------------------------------------------------------------------------
// Launch
// ----------------------------------------------------------------------------
extern "C" void kernel_launch(void* const* d_in, const int* in_sizes, int n_in,
                              void* d_out, int out_size)
{
    const float* x  = (const float*)d_in[0];  // [T,B,H]
    const float* W1 = (const float*)d_in[1];  // [H,H]
    const float* W2 = (const float*)d_in[2];  // [H,H]
    float* out = (float*)d_out;               // [T,B,H]

    float *xf, *xp, *w1t;
    uint16_t *sp, *w2h, *w2l;
    int *cnt, *list;
    cudaGetSymbolAddress((void**)&xf, g_xfix);
    cudaGetSymbolAddress((void**)&xp, g_xproj);
    cudaGetSymbolAddress((void**)&sp, g_spk);
    cudaGetSymbolAddress((void**)&w1t, g_w1t);
    cudaGetSymbolAddress((void**)&w2h, g_w2h);
    cudaGetSymbolAddress((void**)&w2l, g_w2l);
    cudaGetSymbolAddress((void**)&cnt, g_cnt);
    cudaGetSymbolAddress((void**)&list, g_list);

    cudaFuncSetAttribute(gemm_tf32_mma,
                         cudaFuncAttributeMaxDynamicSharedMemorySize, SMEM_DYN);
    cudaFuncSetAttribute(gemm_bf16_split,
                         cudaFuncAttributeMaxDynamicSharedMemorySize, SMEM2_DYN);

    // Round W1 (tf32) and split W2 (bf16 hi/lo); zero flag counters.
    round_w<<<(2 * WF4) / 256, 256>>>(W1, w1t, W2, w2h, w2l, cnt);

    dim3 grid(H_DIM / BN, M_DIM / BM);  // (8, 64)

    // GEMM1 approx (tf32): x_proj ~= x @ W1^T
    gemm_tf32_mma<<<grid, NT_GEMM, SMEM_DYN>>>(x, w1t, xp);

    // LIF scan + flag marginal lanes (bf16 spikes)
    scan_flag<<<(BH / 4) / 256, 256>>>(xp, sp, cnt, list);

    // Exact fp32 recompute of flagged columns, then exact LIF rerun
    fixup_gemm<<<dim3(B_DIM, 8), 256>>>(x, W1, cnt, list, xf);
    fixup_lif<<<(B_DIM * 1024) / 256, 256>>>(xf, cnt, list, sp);

    // GEMM2 (bf16 2-term split): out = spk @ W2^T
    gemm_bf16_split<<<grid, 128, SMEM2_DYN>>>(sp, w2h, w2l, out);
}